// round 13
// baseline (speedup 1.0000x reference)
#include <cuda_runtime.h>
#include <cuda_fp16.h>
#include <math.h>
#include <stdint.h>

// ---------------- problem constants ----------------
#define B_ 512
#define D_ 512
#define C_ 100000

#define S_F    30.0f
#define COSM_F 0.8775825618903728f
#define SINM_F 0.479425538604203f
#define TH_F  (-0.8775825618903728f)
#define MM_F   0.2397127693021015f

#define NTN   782            // n-tiles (128 rows each)
#define DELAY 16             // n-tile lead of wprep over gemm in bid order
#define GRP   20             // 16 wprep pieces + 4 gemm m-tiles per group
#define TOTB  (NTN * GRP + 4 * DELAY)

// ---------------- device scratch ----------------
__device__ __half g_Xh[B_ * D_];
__device__ __half g_Wh[(size_t)C_ * D_];
__device__ int g_label[B_];
__device__ int g_cnt[NTN];

// ---------------- helpers ----------------
__device__ __forceinline__ uint32_t smem_u32(const void* p) {
    uint32_t a;
    asm("{ .reg .u64 t; cvta.to.shared.u64 t, %1; cvt.u32.u64 %0, t; }" : "=r"(a) : "l"(p));
    return a;
}

#define CP16(sm, gp, sz) \
    asm volatile("cp.async.cg.shared.global [%0], [%1], 16, %2;" \
                 :: "r"(sm), "l"(gp), "r"(sz) : "memory")

#define LDSM4(r, addr) \
    asm volatile("ldmatrix.sync.aligned.m8n8.x4.shared.b16 {%0,%1,%2,%3}, [%4];" \
                 : "=r"((r)[0]), "=r"((r)[1]), "=r"((r)[2]), "=r"((r)[3]) : "r"(addr))

#define MMA(acc, a, b) \
    asm volatile("mma.sync.aligned.m16n8k16.row.col.f32.f16.f16.f32 " \
                 "{%0,%1,%2,%3},{%4,%5,%6,%7},{%8,%9},{%0,%1,%2,%3};" \
                 : "+f"((acc)[0]), "+f"((acc)[1]), "+f"((acc)[2]), "+f"((acc)[3]) \
                 : "r"((a)[0]), "r"((a)[1]), "r"((a)[2]), "r"((a)[3]), \
                   "r"((b)[0]), "r"((b)[1]))

__device__ __forceinline__ uint32_t h2u(__half2 h) {
    return *reinterpret_cast<uint32_t*>(&h);
}

__device__ __forceinline__ float arcf(float c, bool isl) {
    c = fminf(1.0f, fmaxf(-1.0f, c));
    float s2 = fminf(1.0f, fmaxf(1e-9f, 1.0f - c * c));
    float sn;
    asm("sqrt.approx.f32 %0, %1;" : "=f"(sn) : "f"(s2));
    float phi = c * COSM_F - sn * SINM_F;
    phi = (c > TH_F) ? phi : (c - MM_F);
    return (isl ? phi : c) * S_F;
}

// ---------------- X prep: normalize X, labels, zero counters ----------------
// 782 blocks: all zero g_cnt[b]; blocks < 512 also do X row b.
__global__ void xprep_kernel(const float* __restrict__ X, const int* __restrict__ raw) {
    int b = blockIdx.x;
    int t = threadIdx.x;  // 128
    if (t == 0) g_cnt[b] = 0;
    if (b >= B_) return;
    const float4* xf = reinterpret_cast<const float4*>(X + (size_t)b * D_);
    float4 v = xf[t];
    float s = v.x * v.x + v.y * v.y + v.z * v.z + v.w * v.w;
#pragma unroll
    for (int o = 16; o > 0; o >>= 1) s += __shfl_xor_sync(0xffffffffu, s, o);
    __shared__ float ws[4];
    if ((t & 31) == 0) ws[t >> 5] = s;
    __syncthreads();
    float tot = ws[0] + ws[1] + ws[2] + ws[3];
    float inv = 1.0f / fmaxf(sqrtf(tot), 1e-12f);
    uint2 hv;
    hv.x = h2u(__floats2half2_rn(v.x * inv, v.y * inv));
    hv.y = h2u(__floats2half2_rn(v.z * inv, v.w * inv));
    *reinterpret_cast<uint2*>(g_Xh + (size_t)b * D_ + t * 4) = hv;

    // label decode: int64 layout iff first 8 odd int32 words are all zero
    if (t == 0) {
        int odd = raw[1] | raw[3] | raw[5] | raw[7] | raw[9] | raw[11] | raw[13] | raw[15];
        g_label[b] = (odd == 0) ? raw[2 * b] : raw[b];
    }
}

// ---------------- fused wprep + GEMM + ArcFace ----------------
#define A_OFF 0
#define B_OFF 16384
#define STAGE_SZ 32768
#define SMEM_TOTAL (3 * STAGE_SZ)   // 98304

__global__ __launch_bounds__(256, 2)
void arcface_fused_kernel(const float* __restrict__ W, float* __restrict__ out) {
    const int bid = blockIdx.x;
    const int tid = threadIdx.x;
    const int g = bid / GRP;
    const int r = bid - g * GRP;

    int nt, mt;
    if (g < NTN) {
        if (r < 16) {
            // ======== wprep piece: 8 W rows, one warp per row ========
            int p = g * 16 + r;           // piece index; rows 8p..8p+7
            int w = tid >> 5, l = tid & 31;
            int row = p * 8 + w;
            if (row < C_) {
                const float4* src = reinterpret_cast<const float4*>(W + (size_t)row * D_);
                float4 v[4];
#pragma unroll
                for (int i = 0; i < 4; i++) v[i] = src[l + 32 * i];
                float s = 0.f;
#pragma unroll
                for (int i = 0; i < 4; i++)
                    s += v[i].x * v[i].x + v[i].y * v[i].y + v[i].z * v[i].z + v[i].w * v[i].w;
#pragma unroll
                for (int o = 16; o > 0; o >>= 1) s += __shfl_xor_sync(0xffffffffu, s, o);
                float inv = 1.0f / fmaxf(sqrtf(s), 1e-12f);
                uint2* dst = reinterpret_cast<uint2*>(g_Wh + (size_t)row * D_);
#pragma unroll
                for (int i = 0; i < 4; i++) {
                    uint2 hv;
                    hv.x = h2u(__floats2half2_rn(v[i].x * inv, v[i].y * inv));
                    hv.y = h2u(__floats2half2_rn(v[i].z * inv, v[i].w * inv));
                    dst[l + 32 * i] = hv;
                }
            }
            __threadfence();
            __syncthreads();
            if (tid == 0) atomicAdd(&g_cnt[g], 1);   // release: tile g has +1/16 pieces
            return;
        }
        nt = g - DELAY;
        mt = r - 16;
        if (nt < 0) return;
    } else {
        int k = bid - NTN * GRP;
        nt = NTN - DELAY + (k >> 2);
        mt = k & 3;
    }

    // ======== GEMM block (R4-validated config) ========
    extern __shared__ char Smem[];
    __shared__ int slab[128];
    const uint32_t sb = smem_u32(Smem);
    const int lane = tid & 31;
    const int wid = tid >> 5;
    const int m0 = mt * 128;
    const int n0 = nt * 128;
    const int mW = (wid >> 2) * 64;
    const int nW = (wid & 3) * 32;

    // acquire: wait until this n-tile's 16 wprep pieces are done
    if (tid == 0) {
        while (atomicAdd(&g_cnt[nt], 0) < 16) __nanosleep(64);
        __threadfence();
    }
    __syncthreads();

    if (tid < 128) slab[tid] = g_label[m0 + tid];

    float acc[4][4][4];
#pragma unroll
    for (int i = 0; i < 4; i++)
#pragma unroll
        for (int j = 0; j < 4; j++)
#pragma unroll
            for (int q = 0; q < 4; q++) acc[i][j][q] = 0.0f;

    const int arow = mW + (lane & 7) + ((lane >> 3) & 1) * 8;
    const int acol = ((lane >> 4) & 1) * 16;
    const int brow = nW + ((lane >> 4) & 1) * 8 + (lane & 7);
    const int bcol = ((lane >> 3) & 1) * 16;
    const int sx   = (lane & 7) * 16;

    auto load_stage = [&](int kc, int st) {
        uint32_t base = sb + st * STAGE_SZ;
#pragma unroll
        for (int j = 0; j < 4; j++) {
            int idx = tid + 256 * j;
            int rr = idx >> 3, c = idx & 7;
            uint32_t doff = (uint32_t)(rr * 128 + ((c * 16) ^ ((rr & 7) * 16)));
            size_t abyt = (size_t)(m0 + rr) * (D_ * 2) + kc * 128 + c * 16;
            CP16(base + A_OFF + doff, (const char*)g_Xh + abyt, 16);
            int n = n0 + rr;
            int ok = (n < C_) ? 16 : 0;
            int nn = (n < C_) ? n : 0;
            size_t bbyt = (size_t)nn * (D_ * 2) + kc * 128 + c * 16;
            CP16(base + B_OFF + doff, (const char*)g_Wh + bbyt, ok);
        }
    };

    auto compute_stage = [&](int st) {
        const uint32_t Ab = sb + st * STAGE_SZ + A_OFF;
        const uint32_t Bb = sb + st * STAGE_SZ + B_OFF;
#pragma unroll
        for (int gg = 0; gg < 4; gg++) {
            uint32_t bh[4][2];
#pragma unroll
            for (int jp = 0; jp < 2; jp++) {
                uint32_t boff = (uint32_t)((brow + 16 * jp) * 128 + ((gg * 32 + bcol) ^ sx));
                uint32_t t4[4];
                LDSM4(t4, Bb + boff);
                bh[2 * jp][0] = t4[0]; bh[2 * jp][1] = t4[1];
                bh[2 * jp + 1][0] = t4[2]; bh[2 * jp + 1][1] = t4[3];
            }
#pragma unroll
            for (int i = 0; i < 4; i++) {
                uint32_t a4[4];
                uint32_t aoff = (uint32_t)((arow + 16 * i) * 128 + ((gg * 32 + acol) ^ sx));
                LDSM4(a4, Ab + aoff);
#pragma unroll
                for (int j = 0; j < 4; j++) MMA(acc[i][j], a4, bh[j]);
            }
        }
    };

    load_stage(0, 0);
    asm volatile("cp.async.commit_group;" ::: "memory");
    load_stage(1, 1);
    asm volatile("cp.async.commit_group;" ::: "memory");
    load_stage(2, 2);
    asm volatile("cp.async.commit_group;" ::: "memory");

    for (int kc = 0; kc < 8; kc++) {
        asm volatile("cp.async.wait_group 2;" ::: "memory");
        __syncthreads();
        compute_stage(kc % 3);
        __syncthreads();
        if (kc + 3 < 8) load_stage(kc + 3, kc % 3);
        asm volatile("cp.async.commit_group;" ::: "memory");
    }

#pragma unroll
    for (int i = 0; i < 4; i++) {
        int lm = mW + i * 16 + (lane >> 2);
        int gm = m0 + lm;
        int lab0 = slab[lm];
        int lab1 = slab[lm + 8];
#pragma unroll
        for (int j = 0; j < 4; j++) {
            int col = n0 + nW + j * 8 + (lane & 3) * 2;
            if (col < C_) {   // C_ even -> pair stays in-bounds together
                float2 v0, v1;
                v0.x = arcf(acc[i][j][0], col == lab0);
                v0.y = arcf(acc[i][j][1], col + 1 == lab0);
                v1.x = arcf(acc[i][j][2], col == lab1);
                v1.y = arcf(acc[i][j][3], col + 1 == lab1);
                *reinterpret_cast<float2*>(out + (size_t)gm * C_ + col) = v0;
                *reinterpret_cast<float2*>(out + (size_t)(gm + 8) * C_ + col) = v1;
            }
        }
    }
}

// ---------------- launch ----------------
extern "C" void kernel_launch(void* const* d_in, const int* in_sizes, int n_in,
                              void* d_out, int out_size) {
    const float* X = nullptr;
    const float* W = nullptr;
    const void*  L = nullptr;

    for (int i = 0; i < n_in; i++) {
        int s = in_sizes[i];
        if (s == B_ * D_)      X = (const float*)d_in[i];
        else if (s == C_ * D_) W = (const float*)d_in[i];
        else if (s == B_)      L = d_in[i];
    }
    if (!X) X = (const float*)d_in[0];
    if (!L) L = d_in[1];
    if (!W) W = (const float*)d_in[2];

    float* out = (float*)d_out;

    xprep_kernel<<<NTN, 128>>>(X, (const int*)L);

    cudaFuncSetAttribute(arcface_fused_kernel,
                         cudaFuncAttributeMaxDynamicSharedMemorySize, SMEM_TOTAL);
    arcface_fused_kernel<<<TOTB, 256, SMEM_TOTAL>>>(W, out);
    (void)out_size;
}

// round 14
// speedup vs baseline: 1.1322x; 1.1322x over previous
#include <cuda_runtime.h>
#include <cuda_fp16.h>
#include <math.h>
#include <stdint.h>

// ---------------- problem constants ----------------
#define B_ 512
#define D_ 512
#define C_ 100000
#define NTN 782              // n-tiles of 128 rows (last partial: 96)

#define S_F    30.0f
#define COSM_F 0.8775825618903728f
#define SINM_F 0.479425538604203f
#define TH_F  (-0.8775825618903728f)
#define MM_F   0.2397127693021015f

// ---------------- device scratch ----------------
__device__ __half g_Xh[B_ * D_];
__device__ __half g_Wh[(size_t)C_ * D_];
__device__ int g_label[B_];
__device__ int g_flag[NTN];

// ---------------- helpers ----------------
__device__ __forceinline__ uint32_t smem_u32(const void* p) {
    uint32_t a;
    asm("{ .reg .u64 t; cvta.to.shared.u64 t, %1; cvt.u32.u64 %0, t; }" : "=r"(a) : "l"(p));
    return a;
}

#define CP16(sm, gp, sz) \
    asm volatile("cp.async.cg.shared.global [%0], [%1], 16, %2;" \
                 :: "r"(sm), "l"(gp), "r"(sz) : "memory")

#define LDSM4(r, addr) \
    asm volatile("ldmatrix.sync.aligned.m8n8.x4.shared.b16 {%0,%1,%2,%3}, [%4];" \
                 : "=r"((r)[0]), "=r"((r)[1]), "=r"((r)[2]), "=r"((r)[3]) : "r"(addr))

#define MMA(acc, a, b) \
    asm volatile("mma.sync.aligned.m16n8k16.row.col.f32.f16.f16.f32 " \
                 "{%0,%1,%2,%3},{%4,%5,%6,%7},{%8,%9},{%0,%1,%2,%3};" \
                 : "+f"((acc)[0]), "+f"((acc)[1]), "+f"((acc)[2]), "+f"((acc)[3]) \
                 : "r"((a)[0]), "r"((a)[1]), "r"((a)[2]), "r"((a)[3]), \
                   "r"((b)[0]), "r"((b)[1]))

#define STG2_CS(ptr, vx, vy) \
    asm volatile("st.global.cs.v2.f32 [%0], {%1, %2};" \
                 :: "l"(ptr), "f"(vx), "f"(vy) : "memory")

__device__ __forceinline__ uint32_t h2u(__half2 h) {
    return *reinterpret_cast<uint32_t*>(&h);
}

__device__ __forceinline__ float arcf(float c, bool isl) {
    c = fminf(1.0f, fmaxf(-1.0f, c));
    float s2 = fminf(1.0f, fmaxf(1e-9f, 1.0f - c * c));
    float sn;
    asm("sqrt.approx.f32 %0, %1;" : "=f"(sn) : "f"(s2));
    float phi = c * COSM_F - sn * SINM_F;
    phi = (c > TH_F) ? phi : (c - MM_F);
    return (isl ? phi : c) * S_F;
}

// ---------------- X prep: normalize X, labels, zero flags ----------------
// 782 blocks: all zero g_flag[b]; blocks < 512 also prep X row b.
__global__ void xprep_kernel(const float* __restrict__ X, const int* __restrict__ raw) {
    int b = blockIdx.x;
    int t = threadIdx.x;  // 128
    if (t == 0) g_flag[b] = 0;
    if (b >= B_) return;
    const float4* xf = reinterpret_cast<const float4*>(X + (size_t)b * D_);
    float4 v = xf[t];
    float s = v.x * v.x + v.y * v.y + v.z * v.z + v.w * v.w;
#pragma unroll
    for (int o = 16; o > 0; o >>= 1) s += __shfl_xor_sync(0xffffffffu, s, o);
    __shared__ float ws[4];
    if ((t & 31) == 0) ws[t >> 5] = s;
    __syncthreads();
    float tot = ws[0] + ws[1] + ws[2] + ws[3];
    float inv = 1.0f / fmaxf(sqrtf(tot), 1e-12f);
    uint2 hv;
    hv.x = h2u(__floats2half2_rn(v.x * inv, v.y * inv));
    hv.y = h2u(__floats2half2_rn(v.z * inv, v.w * inv));
    *reinterpret_cast<uint2*>(g_Xh + (size_t)b * D_ + t * 4) = hv;

    // label decode: int64 layout iff first 8 odd int32 words are all zero
    if (t == 0) {
        int odd = raw[1] | raw[3] | raw[5] | raw[7] | raw[9] | raw[11] | raw[13] | raw[15];
        g_label[b] = (odd == 0) ? raw[2 * b] : raw[b];
    }
}

// ---------------- fused convert-on-first-touch GEMM + ArcFace ----------------
#define A_OFF 0
#define B_OFF 16384
#define STAGE_SZ 32768
#define SMEM_TOTAL (3 * STAGE_SZ)   // 98304

__global__ __launch_bounds__(256, 2)
void arcface_fused_kernel(const float* __restrict__ W, float* __restrict__ out) {
    const int bid = blockIdx.x;
    const int tid = threadIdx.x;
    const int mt = bid / NTN;          // 0..3, n-major: mt=0 blocks come first
    const int nt = bid - mt * NTN;     // 0..781
    const int m0 = mt * 128;
    const int n0 = nt * 128;

    extern __shared__ char Smem[];
    __shared__ int slab[128];
    const uint32_t sb = smem_u32(Smem);
    const int lane = tid & 31;
    const int wid = tid >> 5;
    const int mW = (wid >> 2) * 64;    // warp tile 64x32
    const int nW = (wid & 3) * 32;

    if (mt == 0) {
        // ---- convert this n-tile's W rows: fp32 -> normalized fp16 ----
        // warp-per-row, 16 passes of 8 rows. Pure DRAM phase; overlaps with
        // other resident blocks' GEMM compute after wave 1.
        for (int it = 0; it < 16; it++) {
            int row = n0 + it * 8 + wid;
            if (row < C_) {
                const float4* src = reinterpret_cast<const float4*>(W + (size_t)row * D_);
                float4 v[4];
#pragma unroll
                for (int i = 0; i < 4; i++) v[i] = src[lane + 32 * i];
                float s = 0.f;
#pragma unroll
                for (int i = 0; i < 4; i++)
                    s += v[i].x * v[i].x + v[i].y * v[i].y + v[i].z * v[i].z + v[i].w * v[i].w;
#pragma unroll
                for (int o = 16; o > 0; o >>= 1) s += __shfl_xor_sync(0xffffffffu, s, o);
                float inv = 1.0f / fmaxf(sqrtf(s), 1e-12f);
                uint2* dst = reinterpret_cast<uint2*>(g_Wh + (size_t)row * D_);
#pragma unroll
                for (int i = 0; i < 4; i++) {
                    uint2 hv;
                    hv.x = h2u(__floats2half2_rn(v[i].x * inv, v[i].y * inv));
                    hv.y = h2u(__floats2half2_rn(v[i].z * inv, v[i].w * inv));
                    dst[lane + 32 * i] = hv;
                }
            }
        }
        __threadfence();
        __syncthreads();
        if (tid == 0) atomicExch(&g_flag[nt], 1);   // release
    } else {
        // ---- acquire: mt=0 block for this nt is >=782 bids earlier ----
        if (tid == 0) {
            while (atomicAdd(&g_flag[nt], 0) == 0) __nanosleep(128);
            __threadfence();
        }
        __syncthreads();
    }

    if (tid < 128) slab[tid] = g_label[m0 + tid];

    float acc[4][4][4];
#pragma unroll
    for (int i = 0; i < 4; i++)
#pragma unroll
        for (int j = 0; j < 4; j++)
#pragma unroll
            for (int q = 0; q < 4; q++) acc[i][j][q] = 0.0f;

    // ldmatrix lane-address components
    const int arow = mW + (lane & 7) + ((lane >> 3) & 1) * 8;   // + 16*i
    const int acol = ((lane >> 4) & 1) * 16;                    // + 32*g
    const int brow = nW + ((lane >> 4) & 1) * 8 + (lane & 7);   // + 16*jp
    const int bcol = ((lane >> 3) & 1) * 16;
    const int sx   = (lane & 7) * 16;                           // swizzle xor

    auto load_stage = [&](int kc, int st) {
        uint32_t base = sb + st * STAGE_SZ;
#pragma unroll
        for (int j = 0; j < 4; j++) {
            int idx = tid + 256 * j;
            int rr = idx >> 3, c = idx & 7;
            uint32_t doff = (uint32_t)(rr * 128 + ((c * 16) ^ ((rr & 7) * 16)));
            size_t abyt = (size_t)(m0 + rr) * (D_ * 2) + kc * 128 + c * 16;
            CP16(base + A_OFF + doff, (const char*)g_Xh + abyt, 16);
            int n = n0 + rr;
            int ok = (n < C_) ? 16 : 0;
            int nn = (n < C_) ? n : 0;
            size_t bbyt = (size_t)nn * (D_ * 2) + kc * 128 + c * 16;
            CP16(base + B_OFF + doff, (const char*)g_Wh + bbyt, ok);
        }
    };

    auto compute_stage = [&](int st) {
        const uint32_t Ab = sb + st * STAGE_SZ + A_OFF;
        const uint32_t Bb = sb + st * STAGE_SZ + B_OFF;
#pragma unroll
        for (int g = 0; g < 4; g++) {
            uint32_t bh[4][2];
#pragma unroll
            for (int jp = 0; jp < 2; jp++) {
                uint32_t boff = (uint32_t)((brow + 16 * jp) * 128 + ((g * 32 + bcol) ^ sx));
                uint32_t t4[4];
                LDSM4(t4, Bb + boff);
                bh[2 * jp][0] = t4[0]; bh[2 * jp][1] = t4[1];
                bh[2 * jp + 1][0] = t4[2]; bh[2 * jp + 1][1] = t4[3];
            }
#pragma unroll
            for (int i = 0; i < 4; i++) {
                uint32_t a4[4];
                uint32_t aoff = (uint32_t)((arow + 16 * i) * 128 + ((g * 32 + acol) ^ sx));
                LDSM4(a4, Ab + aoff);
#pragma unroll
                for (int j = 0; j < 4; j++) MMA(acc[i][j], a4, bh[j]);
            }
        }
    };

    // ---- prologue: fill stages 0..2 ----
    load_stage(0, 0);
    asm volatile("cp.async.commit_group;" ::: "memory");
    load_stage(1, 1);
    asm volatile("cp.async.commit_group;" ::: "memory");
    load_stage(2, 2);
    asm volatile("cp.async.commit_group;" ::: "memory");

    // ---- main loop (R4 schedule) ----
    for (int kc = 0; kc < 8; kc++) {
        asm volatile("cp.async.wait_group 2;" ::: "memory");
        __syncthreads();
        compute_stage(kc % 3);
        __syncthreads();
        if (kc + 3 < 8) load_stage(kc + 3, kc % 3);
        asm volatile("cp.async.commit_group;" ::: "memory");
    }

    // ---- epilogue: ArcFace + streaming stores (protect L2 for g_Wh) ----
#pragma unroll
    for (int i = 0; i < 4; i++) {
        int lm = mW + i * 16 + (lane >> 2);
        int gm = m0 + lm;
        int lab0 = slab[lm];
        int lab1 = slab[lm + 8];
#pragma unroll
        for (int j = 0; j < 4; j++) {
            int col = n0 + nW + j * 8 + (lane & 3) * 2;
            if (col < C_) {   // C_ even -> pair stays in-bounds together
                float a0 = arcf(acc[i][j][0], col == lab0);
                float a1 = arcf(acc[i][j][1], col + 1 == lab0);
                float b0 = arcf(acc[i][j][2], col == lab1);
                float b1 = arcf(acc[i][j][3], col + 1 == lab1);
                STG2_CS(out + (size_t)gm * C_ + col, a0, a1);
                STG2_CS(out + (size_t)(gm + 8) * C_ + col, b0, b1);
            }
        }
    }
}

// ---------------- launch ----------------
extern "C" void kernel_launch(void* const* d_in, const int* in_sizes, int n_in,
                              void* d_out, int out_size) {
    const float* X = nullptr;
    const float* W = nullptr;
    const void*  L = nullptr;

    for (int i = 0; i < n_in; i++) {
        int s = in_sizes[i];
        if (s == B_ * D_)      X = (const float*)d_in[i];
        else if (s == C_ * D_) W = (const float*)d_in[i];
        else if (s == B_)      L = d_in[i];
    }
    if (!X) X = (const float*)d_in[0];
    if (!L) L = d_in[1];
    if (!W) W = (const float*)d_in[2];

    float* out = (float*)d_out;

    xprep_kernel<<<NTN, 128>>>(X, (const int*)L);

    cudaFuncSetAttribute(arcface_fused_kernel,
                         cudaFuncAttributeMaxDynamicSharedMemorySize, SMEM_TOTAL);
    arcface_fused_kernel<<<4 * NTN, 256, SMEM_TOTAL>>>(W, out);
    (void)out_size;
}

// round 15
// speedup vs baseline: 1.1795x; 1.0417x over previous
#include <cuda_runtime.h>
#include <cuda_fp16.h>
#include <math.h>
#include <stdint.h>

// ---------------- problem constants ----------------
#define B_ 512
#define D_ 512
#define C_ 100000
#define NTN 782              // n-tiles of 128 rows (last partial: 96)
#define DELAY 128            // tile lead of converter over consumers (512 bids)
#define TAILB (3 * DELAY)    // appended blocks for last DELAY tiles' mt=1..3

#define S_F    30.0f
#define COSM_F 0.8775825618903728f
#define SINM_F 0.479425538604203f
#define TH_F  (-0.8775825618903728f)
#define MM_F   0.2397127693021015f

// ---------------- device scratch ----------------
__device__ __half g_Xh[B_ * D_];
__device__ __half g_Wh[(size_t)C_ * D_];
__device__ int g_label[B_];
__device__ int g_flag[NTN];

// ---------------- helpers ----------------
__device__ __forceinline__ uint32_t smem_u32(const void* p) {
    uint32_t a;
    asm("{ .reg .u64 t; cvta.to.shared.u64 t, %1; cvt.u32.u64 %0, t; }" : "=r"(a) : "l"(p));
    return a;
}

#define CP16(sm, gp, sz) \
    asm volatile("cp.async.cg.shared.global [%0], [%1], 16, %2;" \
                 :: "r"(sm), "l"(gp), "r"(sz) : "memory")

#define LDSM4(r, addr) \
    asm volatile("ldmatrix.sync.aligned.m8n8.x4.shared.b16 {%0,%1,%2,%3}, [%4];" \
                 : "=r"((r)[0]), "=r"((r)[1]), "=r"((r)[2]), "=r"((r)[3]) : "r"(addr))

#define MMA(acc, a, b) \
    asm volatile("mma.sync.aligned.m16n8k16.row.col.f32.f16.f16.f32 " \
                 "{%0,%1,%2,%3},{%4,%5,%6,%7},{%8,%9},{%0,%1,%2,%3};" \
                 : "+f"((acc)[0]), "+f"((acc)[1]), "+f"((acc)[2]), "+f"((acc)[3]) \
                 : "r"((a)[0]), "r"((a)[1]), "r"((a)[2]), "r"((a)[3]), \
                   "r"((b)[0]), "r"((b)[1]))

#define STG2_CS(ptr, vx, vy) \
    asm volatile("st.global.cs.v2.f32 [%0], {%1, %2};" \
                 :: "l"(ptr), "f"(vx), "f"(vy) : "memory")

__device__ __forceinline__ uint32_t h2u(__half2 h) {
    return *reinterpret_cast<uint32_t*>(&h);
}

__device__ __forceinline__ float arcf(float c, bool isl) {
    c = fminf(1.0f, fmaxf(-1.0f, c));
    float s2 = fminf(1.0f, fmaxf(1e-9f, 1.0f - c * c));
    float sn;
    asm("sqrt.approx.f32 %0, %1;" : "=f"(sn) : "f"(s2));
    float phi = c * COSM_F - sn * SINM_F;
    phi = (c > TH_F) ? phi : (c - MM_F);
    return (isl ? phi : c) * S_F;
}

// ---------------- X prep: normalize X, labels, zero flags ----------------
__global__ void xprep_kernel(const float* __restrict__ X, const int* __restrict__ raw) {
    int b = blockIdx.x;
    int t = threadIdx.x;  // 128
    if (t == 0) g_flag[b] = 0;
    if (b >= B_) return;
    const float4* xf = reinterpret_cast<const float4*>(X + (size_t)b * D_);
    float4 v = xf[t];
    float s = v.x * v.x + v.y * v.y + v.z * v.z + v.w * v.w;
#pragma unroll
    for (int o = 16; o > 0; o >>= 1) s += __shfl_xor_sync(0xffffffffu, s, o);
    __shared__ float ws[4];
    if ((t & 31) == 0) ws[t >> 5] = s;
    __syncthreads();
    float tot = ws[0] + ws[1] + ws[2] + ws[3];
    float inv = 1.0f / fmaxf(sqrtf(tot), 1e-12f);
    uint2 hv;
    hv.x = h2u(__floats2half2_rn(v.x * inv, v.y * inv));
    hv.y = h2u(__floats2half2_rn(v.z * inv, v.w * inv));
    *reinterpret_cast<uint2*>(g_Xh + (size_t)b * D_ + t * 4) = hv;

    // label decode: int64 layout iff first 8 odd int32 words are all zero
    if (t == 0) {
        int odd = raw[1] | raw[3] | raw[5] | raw[7] | raw[9] | raw[11] | raw[13] | raw[15];
        g_label[b] = (odd == 0) ? raw[2 * b] : raw[b];
    }
}

// ---------------- fused convert-interleaved GEMM + ArcFace ----------------
#define A_OFF 0
#define B_OFF 16384
#define STAGE_SZ 32768
#define SMEM_TOTAL (3 * STAGE_SZ)   // 98304

__global__ __launch_bounds__(256, 2)
void arcface_fused_kernel(const float* __restrict__ W, float* __restrict__ out) {
    const int bid = blockIdx.x;
    const int tid = threadIdx.x;

    // ---- bid -> (nt, mt); converters (mt=0) spread 1-in-4 ----
    int nt, mt;
    if (bid < 4 * NTN) {
        int grp = bid >> 2;
        int r = bid & 3;
        if (r == 0) { nt = grp; mt = 0; }
        else {
            nt = grp - DELAY;
            mt = r;
            if (nt < 0) return;   // early no-op slots
        }
    } else {
        int k = bid - 4 * NTN;           // 0..TAILB-1
        nt = (NTN - DELAY) + k / 3;
        mt = 1 + k % 3;
    }
    const int m0 = mt * 128;
    const int n0 = nt * 128;

    extern __shared__ char Smem[];
    __shared__ int slab[128];
    const uint32_t sb = smem_u32(Smem);
    const int lane = tid & 31;
    const int wid = tid >> 5;
    const int mW = (wid >> 2) * 64;    // warp tile 64x32
    const int nW = (wid & 3) * 32;

    if (mt == 0) {
        // ---- convert this n-tile's W rows: fp32 -> normalized fp16 ----
        for (int it = 0; it < 16; it++) {
            int row = n0 + it * 8 + wid;
            if (row < C_) {
                const float4* src = reinterpret_cast<const float4*>(W + (size_t)row * D_);
                float4 v[4];
#pragma unroll
                for (int i = 0; i < 4; i++) v[i] = src[lane + 32 * i];
                float s = 0.f;
#pragma unroll
                for (int i = 0; i < 4; i++)
                    s += v[i].x * v[i].x + v[i].y * v[i].y + v[i].z * v[i].z + v[i].w * v[i].w;
#pragma unroll
                for (int o = 16; o > 0; o >>= 1) s += __shfl_xor_sync(0xffffffffu, s, o);
                float inv = 1.0f / fmaxf(sqrtf(s), 1e-12f);
                uint2* dst = reinterpret_cast<uint2*>(g_Wh + (size_t)row * D_);
#pragma unroll
                for (int i = 0; i < 4; i++) {
                    uint2 hv;
                    hv.x = h2u(__floats2half2_rn(v[i].x * inv, v[i].y * inv));
                    hv.y = h2u(__floats2half2_rn(v[i].z * inv, v[i].w * inv));
                    dst[lane + 32 * i] = hv;
                }
            }
        }
        __threadfence();
        __syncthreads();
        if (tid == 0) atomicExch(&g_flag[nt], 1);   // release
    } else {
        // ---- acquire: converter sits 512 bids (~1.7 waves) earlier ----
        if (tid == 0) {
            while (atomicAdd(&g_flag[nt], 0) == 0) __nanosleep(128);
            __threadfence();
        }
        __syncthreads();
    }

    if (tid < 128) slab[tid] = g_label[m0 + tid];

    float acc[4][4][4];
#pragma unroll
    for (int i = 0; i < 4; i++)
#pragma unroll
        for (int j = 0; j < 4; j++)
#pragma unroll
            for (int q = 0; q < 4; q++) acc[i][j][q] = 0.0f;

    // ldmatrix lane-address components
    const int arow = mW + (lane & 7) + ((lane >> 3) & 1) * 8;   // + 16*i
    const int acol = ((lane >> 4) & 1) * 16;                    // + 32*g
    const int brow = nW + ((lane >> 4) & 1) * 8 + (lane & 7);   // + 16*jp
    const int bcol = ((lane >> 3) & 1) * 16;
    const int sx   = (lane & 7) * 16;                           // swizzle xor

    auto load_stage = [&](int kc, int st) {
        uint32_t base = sb + st * STAGE_SZ;
#pragma unroll
        for (int j = 0; j < 4; j++) {
            int idx = tid + 256 * j;
            int rr = idx >> 3, c = idx & 7;
            uint32_t doff = (uint32_t)(rr * 128 + ((c * 16) ^ ((rr & 7) * 16)));
            size_t abyt = (size_t)(m0 + rr) * (D_ * 2) + kc * 128 + c * 16;
            CP16(base + A_OFF + doff, (const char*)g_Xh + abyt, 16);
            int n = n0 + rr;
            int ok = (n < C_) ? 16 : 0;
            int nn = (n < C_) ? n : 0;
            size_t bbyt = (size_t)nn * (D_ * 2) + kc * 128 + c * 16;
            CP16(base + B_OFF + doff, (const char*)g_Wh + bbyt, ok);
        }
    };

    auto compute_stage = [&](int st) {
        const uint32_t Ab = sb + st * STAGE_SZ + A_OFF;
        const uint32_t Bb = sb + st * STAGE_SZ + B_OFF;
#pragma unroll
        for (int g = 0; g < 4; g++) {
            uint32_t bh[4][2];
#pragma unroll
            for (int jp = 0; jp < 2; jp++) {
                uint32_t boff = (uint32_t)((brow + 16 * jp) * 128 + ((g * 32 + bcol) ^ sx));
                uint32_t t4[4];
                LDSM4(t4, Bb + boff);
                bh[2 * jp][0] = t4[0]; bh[2 * jp][1] = t4[1];
                bh[2 * jp + 1][0] = t4[2]; bh[2 * jp + 1][1] = t4[3];
            }
#pragma unroll
            for (int i = 0; i < 4; i++) {
                uint32_t a4[4];
                uint32_t aoff = (uint32_t)((arow + 16 * i) * 128 + ((g * 32 + acol) ^ sx));
                LDSM4(a4, Ab + aoff);
#pragma unroll
                for (int j = 0; j < 4; j++) MMA(acc[i][j], a4, bh[j]);
            }
        }
    };

    // ---- prologue: fill stages 0..2 ----
    load_stage(0, 0);
    asm volatile("cp.async.commit_group;" ::: "memory");
    load_stage(1, 1);
    asm volatile("cp.async.commit_group;" ::: "memory");
    load_stage(2, 2);
    asm volatile("cp.async.commit_group;" ::: "memory");

    // ---- main loop (R4 schedule) ----
    for (int kc = 0; kc < 8; kc++) {
        asm volatile("cp.async.wait_group 2;" ::: "memory");
        __syncthreads();
        compute_stage(kc % 3);
        __syncthreads();
        if (kc + 3 < 8) load_stage(kc + 3, kc % 3);
        asm volatile("cp.async.commit_group;" ::: "memory");
    }

    // ---- epilogue: ArcFace + streaming stores ----
#pragma unroll
    for (int i = 0; i < 4; i++) {
        int lm = mW + i * 16 + (lane >> 2);
        int gm = m0 + lm;
        int lab0 = slab[lm];
        int lab1 = slab[lm + 8];
#pragma unroll
        for (int j = 0; j < 4; j++) {
            int col = n0 + nW + j * 8 + (lane & 3) * 2;
            if (col < C_) {   // C_ even -> pair stays in-bounds together
                float a0 = arcf(acc[i][j][0], col == lab0);
                float a1 = arcf(acc[i][j][1], col + 1 == lab0);
                float b0 = arcf(acc[i][j][2], col == lab1);
                float b1 = arcf(acc[i][j][3], col + 1 == lab1);
                STG2_CS(out + (size_t)gm * C_ + col, a0, a1);
                STG2_CS(out + (size_t)(gm + 8) * C_ + col, b0, b1);
            }
        }
    }
}

// ---------------- launch ----------------
extern "C" void kernel_launch(void* const* d_in, const int* in_sizes, int n_in,
                              void* d_out, int out_size) {
    const float* X = nullptr;
    const float* W = nullptr;
    const void*  L = nullptr;

    for (int i = 0; i < n_in; i++) {
        int s = in_sizes[i];
        if (s == B_ * D_)      X = (const float*)d_in[i];
        else if (s == C_ * D_) W = (const float*)d_in[i];
        else if (s == B_)      L = d_in[i];
    }
    if (!X) X = (const float*)d_in[0];
    if (!L) L = d_in[1];
    if (!W) W = (const float*)d_in[2];

    float* out = (float*)d_out;

    xprep_kernel<<<NTN, 128>>>(X, (const int*)L);

    cudaFuncSetAttribute(arcface_fused_kernel,
                         cudaFuncAttributeMaxDynamicSharedMemorySize, SMEM_TOTAL);
    arcface_fused_kernel<<<4 * NTN + TAILB, 256, SMEM_TOTAL>>>(W, out);
    (void)out_size;
}

// round 16
// speedup vs baseline: 1.1908x; 1.0096x over previous
#include <cuda_runtime.h>
#include <cuda_fp16.h>
#include <math.h>
#include <stdint.h>

// ---------------- problem constants ----------------
#define B_ 512
#define D_ 512
#define C_ 100000
#define NTN 782              // n-tiles of 128 rows (last partial: 96)
#define DELAY 128            // group lead of converters over consumers (512 bids)

#define S_F    30.0f
#define COSM_F 0.8775825618903728f
#define SINM_F 0.479425538604203f
#define TH_F  (-0.8775825618903728f)
#define MM_F   0.2397127693021015f

// ---------------- device scratch ----------------
__device__ __half g_Xh[B_ * D_];
__device__ __half g_Wh[(size_t)C_ * D_];
__device__ int g_label[B_];
__device__ int g_cnt[NTN];

// ---------------- helpers ----------------
__device__ __forceinline__ uint32_t smem_u32(const void* p) {
    uint32_t a;
    asm("{ .reg .u64 t; cvta.to.shared.u64 t, %1; cvt.u32.u64 %0, t; }" : "=r"(a) : "l"(p));
    return a;
}

#define CP16(sm, gp, sz) \
    asm volatile("cp.async.cg.shared.global [%0], [%1], 16, %2;" \
                 :: "r"(sm), "l"(gp), "r"(sz) : "memory")

#define LDSM4(r, addr) \
    asm volatile("ldmatrix.sync.aligned.m8n8.x4.shared.b16 {%0,%1,%2,%3}, [%4];" \
                 : "=r"((r)[0]), "=r"((r)[1]), "=r"((r)[2]), "=r"((r)[3]) : "r"(addr))

#define MMA(acc, a, b) \
    asm volatile("mma.sync.aligned.m16n8k16.row.col.f32.f16.f16.f32 " \
                 "{%0,%1,%2,%3},{%4,%5,%6,%7},{%8,%9},{%0,%1,%2,%3};" \
                 : "+f"((acc)[0]), "+f"((acc)[1]), "+f"((acc)[2]), "+f"((acc)[3]) \
                 : "r"((a)[0]), "r"((a)[1]), "r"((a)[2]), "r"((a)[3]), \
                   "r"((b)[0]), "r"((b)[1]))

#define STG2_CS(ptr, vx, vy) \
    asm volatile("st.global.cs.v2.f32 [%0], {%1, %2};" \
                 :: "l"(ptr), "f"(vx), "f"(vy) : "memory")

__device__ __forceinline__ uint32_t h2u(__half2 h) {
    return *reinterpret_cast<uint32_t*>(&h);
}

__device__ __forceinline__ float arcf(float c, bool isl) {
    c = fminf(1.0f, fmaxf(-1.0f, c));
    float s2 = fminf(1.0f, fmaxf(1e-9f, 1.0f - c * c));
    float sn;
    asm("sqrt.approx.f32 %0, %1;" : "=f"(sn) : "f"(s2));
    float phi = c * COSM_F - sn * SINM_F;
    phi = (c > TH_F) ? phi : (c - MM_F);
    return (isl ? phi : c) * S_F;
}

// ---------------- X prep: normalize X, labels, zero counters ----------------
__global__ void xprep_kernel(const float* __restrict__ X, const int* __restrict__ raw) {
    int b = blockIdx.x;
    int t = threadIdx.x;  // 128
    if (t == 0) g_cnt[b] = 0;
    if (b >= B_) return;
    const float4* xf = reinterpret_cast<const float4*>(X + (size_t)b * D_);
    float4 v = xf[t];
    float s = v.x * v.x + v.y * v.y + v.z * v.z + v.w * v.w;
#pragma unroll
    for (int o = 16; o > 0; o >>= 1) s += __shfl_xor_sync(0xffffffffu, s, o);
    __shared__ float ws[4];
    if ((t & 31) == 0) ws[t >> 5] = s;
    __syncthreads();
    float tot = ws[0] + ws[1] + ws[2] + ws[3];
    float inv = 1.0f / fmaxf(sqrtf(tot), 1e-12f);
    uint2 hv;
    hv.x = h2u(__floats2half2_rn(v.x * inv, v.y * inv));
    hv.y = h2u(__floats2half2_rn(v.z * inv, v.w * inv));
    *reinterpret_cast<uint2*>(g_Xh + (size_t)b * D_ + t * 4) = hv;

    // label decode: int64 layout iff first 8 odd int32 words are all zero
    if (t == 0) {
        int odd = raw[1] | raw[3] | raw[5] | raw[7] | raw[9] | raw[11] | raw[13] | raw[15];
        g_label[b] = (odd == 0) ? raw[2 * b] : raw[b];
    }
}

// ---------------- fused quarter-convert + GEMM + ArcFace ----------------
// group g = bid>>2, r = bid&3.
//   convert: quarter r (32 rows) of tile g           (if g < NTN)
//   gemm:    tile nt = g - DELAY, m-tile mt = r      (if nt >= 0)
// Consumers' producers (group nt) sit 4*DELAY = 512 bids earlier -> no deadlock.
#define A_OFF 0
#define B_OFF 16384
#define STAGE_SZ 32768
#define SMEM_TOTAL (3 * STAGE_SZ)   // 98304

__global__ __launch_bounds__(256, 2)
void arcface_fused_kernel(const float* __restrict__ W, float* __restrict__ out) {
    const int bid = blockIdx.x;
    const int tid = threadIdx.x;
    const int g = bid >> 2;
    const int r = bid & 3;
    const int nt = g - DELAY;
    const int mt = r;

    extern __shared__ char Smem[];
    __shared__ int slab[128];
    const uint32_t sb = smem_u32(Smem);
    const int lane = tid & 31;
    const int wid = tid >> 5;
    const int mW = (wid >> 2) * 64;    // warp tile 64x32
    const int nW = (wid & 3) * 32;

    // ---- convert phase: quarter r of tile g (32 rows, warp-per-row x4) ----
    if (g < NTN) {
        int base_row = g * 128 + r * 32;
#pragma unroll
        for (int it = 0; it < 4; it++) {
            int row = base_row + it * 8 + wid;
            if (row < C_) {
                const float4* src = reinterpret_cast<const float4*>(W + (size_t)row * D_);
                float4 v[4];
#pragma unroll
                for (int i = 0; i < 4; i++) v[i] = src[lane + 32 * i];
                float s = 0.f;
#pragma unroll
                for (int i = 0; i < 4; i++)
                    s += v[i].x * v[i].x + v[i].y * v[i].y + v[i].z * v[i].z + v[i].w * v[i].w;
#pragma unroll
                for (int o = 16; o > 0; o >>= 1) s += __shfl_xor_sync(0xffffffffu, s, o);
                float inv = 1.0f / fmaxf(sqrtf(s), 1e-12f);
                uint2* dst = reinterpret_cast<uint2*>(g_Wh + (size_t)row * D_);
#pragma unroll
                for (int i = 0; i < 4; i++) {
                    uint2 hv;
                    hv.x = h2u(__floats2half2_rn(v[i].x * inv, v[i].y * inv));
                    hv.y = h2u(__floats2half2_rn(v[i].z * inv, v[i].w * inv));
                    dst[lane + 32 * i] = hv;
                }
            }
        }
        __threadfence();
        __syncthreads();
        if (tid == 0) atomicAdd(&g_cnt[g], 1);   // release quarter
    }

    if (nt < 0) return;   // head groups: convert-only
    const int m0 = mt * 128;
    const int n0 = nt * 128;

    // ---- acquire: tile nt fully converted (producers 512 bids earlier) ----
    if (tid == 0) {
        while (atomicAdd(&g_cnt[nt], 0) < 4) __nanosleep(128);
        __threadfence();
    }
    __syncthreads();

    if (tid < 128) slab[tid] = g_label[m0 + tid];

    float acc[4][4][4];
#pragma unroll
    for (int i = 0; i < 4; i++)
#pragma unroll
        for (int j = 0; j < 4; j++)
#pragma unroll
            for (int q = 0; q < 4; q++) acc[i][j][q] = 0.0f;

    // ldmatrix lane-address components
    const int arow = mW + (lane & 7) + ((lane >> 3) & 1) * 8;   // + 16*i
    const int acol = ((lane >> 4) & 1) * 16;                    // + 32*g
    const int brow = nW + ((lane >> 4) & 1) * 8 + (lane & 7);   // + 16*jp
    const int bcol = ((lane >> 3) & 1) * 16;
    const int sx   = (lane & 7) * 16;                           // swizzle xor

    auto load_stage = [&](int kc, int st) {
        uint32_t base = sb + st * STAGE_SZ;
#pragma unroll
        for (int j = 0; j < 4; j++) {
            int idx = tid + 256 * j;
            int rr = idx >> 3, c = idx & 7;
            uint32_t doff = (uint32_t)(rr * 128 + ((c * 16) ^ ((rr & 7) * 16)));
            size_t abyt = (size_t)(m0 + rr) * (D_ * 2) + kc * 128 + c * 16;
            CP16(base + A_OFF + doff, (const char*)g_Xh + abyt, 16);
            int n = n0 + rr;
            int ok = (n < C_) ? 16 : 0;
            int nn = (n < C_) ? n : 0;
            size_t bbyt = (size_t)nn * (D_ * 2) + kc * 128 + c * 16;
            CP16(base + B_OFF + doff, (const char*)g_Wh + bbyt, ok);
        }
    };

    auto compute_stage = [&](int st) {
        const uint32_t Ab = sb + st * STAGE_SZ + A_OFF;
        const uint32_t Bb = sb + st * STAGE_SZ + B_OFF;
#pragma unroll
        for (int gg = 0; gg < 4; gg++) {
            uint32_t bh[4][2];
#pragma unroll
            for (int jp = 0; jp < 2; jp++) {
                uint32_t boff = (uint32_t)((brow + 16 * jp) * 128 + ((gg * 32 + bcol) ^ sx));
                uint32_t t4[4];
                LDSM4(t4, Bb + boff);
                bh[2 * jp][0] = t4[0]; bh[2 * jp][1] = t4[1];
                bh[2 * jp + 1][0] = t4[2]; bh[2 * jp + 1][1] = t4[3];
            }
#pragma unroll
            for (int i = 0; i < 4; i++) {
                uint32_t a4[4];
                uint32_t aoff = (uint32_t)((arow + 16 * i) * 128 + ((gg * 32 + acol) ^ sx));
                LDSM4(a4, Ab + aoff);
#pragma unroll
                for (int j = 0; j < 4; j++) MMA(acc[i][j], a4, bh[j]);
            }
        }
    };

    // ---- prologue: fill stages 0..2 ----
    load_stage(0, 0);
    asm volatile("cp.async.commit_group;" ::: "memory");
    load_stage(1, 1);
    asm volatile("cp.async.commit_group;" ::: "memory");
    load_stage(2, 2);
    asm volatile("cp.async.commit_group;" ::: "memory");

    // ---- main loop (R4 schedule) ----
    for (int kc = 0; kc < 8; kc++) {
        asm volatile("cp.async.wait_group 2;" ::: "memory");
        __syncthreads();
        compute_stage(kc % 3);
        __syncthreads();
        if (kc + 3 < 8) load_stage(kc + 3, kc % 3);
        asm volatile("cp.async.commit_group;" ::: "memory");
    }

    // ---- epilogue: ArcFace + streaming stores ----
#pragma unroll
    for (int i = 0; i < 4; i++) {
        int lm = mW + i * 16 + (lane >> 2);
        int gm = m0 + lm;
        int lab0 = slab[lm];
        int lab1 = slab[lm + 8];
#pragma unroll
        for (int j = 0; j < 4; j++) {
            int col = n0 + nW + j * 8 + (lane & 3) * 2;
            if (col < C_) {   // C_ even -> pair stays in-bounds together
                float a0 = arcf(acc[i][j][0], col == lab0);
                float a1 = arcf(acc[i][j][1], col + 1 == lab0);
                float b0 = arcf(acc[i][j][2], col == lab1);
                float b1 = arcf(acc[i][j][3], col + 1 == lab1);
                STG2_CS(out + (size_t)gm * C_ + col, a0, a1);
                STG2_CS(out + (size_t)(gm + 8) * C_ + col, b0, b1);
            }
        }
    }
}

// ---------------- launch ----------------
extern "C" void kernel_launch(void* const* d_in, const int* in_sizes, int n_in,
                              void* d_out, int out_size) {
    const float* X = nullptr;
    const float* W = nullptr;
    const void*  L = nullptr;

    for (int i = 0; i < n_in; i++) {
        int s = in_sizes[i];
        if (s == B_ * D_)      X = (const float*)d_in[i];
        else if (s == C_ * D_) W = (const float*)d_in[i];
        else if (s == B_)      L = d_in[i];
    }
    if (!X) X = (const float*)d_in[0];
    if (!L) L = d_in[1];
    if (!W) W = (const float*)d_in[2];

    float* out = (float*)d_out;

    xprep_kernel<<<NTN, 128>>>(X, (const int*)L);

    cudaFuncSetAttribute(arcface_fused_kernel,
                         cudaFuncAttributeMaxDynamicSharedMemorySize, SMEM_TOTAL);
    arcface_fused_kernel<<<4 * (NTN + DELAY), 256, SMEM_TOTAL>>>(W, out);
    (void)out_size;
}